// round 14
// baseline (speedup 1.0000x reference)
#include <cuda_runtime.h>
#include <cuda_bf16.h>

#define NN    65536
#define NGR   32768
#define HH    64
#define BB    64
#define MAXD  10
#define BKT   128      // bucket capacity per (type,node); max real degree ~70
#define ZR    NN       // zero-row node id (padding target)

// ---- scratch: device globals (no allocation allowed) ----
__device__ __align__(16) float g_h [(size_t)(NN + 1) * HH];   // ping (+ zero row)
__device__ __align__(16) float g_h2[(size_t)(NN + 1) * HH];   // pong (+ zero row)
__device__ __align__(16) int   g_bkt[(size_t)4 * NGR * BKT];  // 64MB dst-bucketed src ids
__device__ int   g_cnt[4][NGR];                               // per-conv-type receive degree
__device__ float g_pooled[BB * HH];

// ---------------- init: pad buckets with ZR, zero counters/pooled/zero-rows ----------------
__global__ void init_kernel() {
    int gid = blockIdx.x * blockDim.x + threadIdx.x;
    const int nbq = 4 * NGR * BKT / 4;
    if (gid < nbq) {
        ((int4*)g_bkt)[gid] = make_int4(ZR, ZR, ZR, ZR);
    } else {
        int r = gid - nbq;
        if (r < 4 * NGR) ((int*)g_cnt)[r] = 0;
        else if (r < 4 * NGR + BB * HH) g_pooled[r - 4 * NGR] = 0.f;
        else if (r < 4 * NGR + BB * HH + HH) {
            int z = r - 4 * NGR - BB * HH;
            g_h [(size_t)ZR * HH + z] = 0.f;
            g_h2[(size_t)ZR * HH + z] = 0.f;
        }
    }
}

// ---------------- single pass: bucket all 4 edge sets ----------------
__global__ void fill_all_kernel(const int* __restrict__ e0, const int* __restrict__ e1,
                                const int* __restrict__ e2, const int* __restrict__ e3,
                                int E0, int E1, int E2, int E3) {
    int e = blockIdx.x * blockDim.x + threadIdx.x;
    const int* ei; int E, t, base;
    if (e < E0)              { ei = e0; E = E0; t = 0; base = 0;   }
    else if ((e -= E0) < E1) { ei = e1; E = E1; t = 1; base = NGR; }
    else if ((e -= E1) < E2) { ei = e2; E = E2; t = 2; base = NGR; }
    else if ((e -= E2) < E3) { ei = e3; E = E3; t = 3; base = 0;   }
    else return;
    int src = __ldg(ei + e);
    int dst = __ldg(ei + E + e);
    int li  = dst - base;
    int slot = atomicAdd(&g_cnt[t][li], 1);
    if (slot < BKT) g_bkt[((size_t)(t * NGR + li) << 7) + slot] = src;
}

// ---------------- embed: h = x @ W(32x64) + b ----------------
__global__ void embed_kernel(const float* __restrict__ x,
                             const float* __restrict__ W,
                             const float* __restrict__ b) {
    int node = blockIdx.x * 8 + (threadIdx.x >> 5);
    int lane = threadIdx.x & 31;
    float xv = x[(size_t)node * 32 + lane];
    int c = lane * 2;
    float2 acc = make_float2(b[c], b[c + 1]);
#pragma unroll 8
    for (int k = 0; k < 32; k++) {
        float xk = __shfl_sync(0xffffffffu, xv, k);
        float2 w = *(const float2*)(W + k * 64 + c);
        acc.x += xk * w.x;
        acc.y += xk * w.y;
    }
    *(float2*)(g_h + (size_t)node * 64 + c) = acc;
}

// ---------------- relu on both current halves ----------------
__global__ void relu2_kernel(float* bg, float* bs) {
    int gid = blockIdx.x * blockDim.x + threadIdx.x;   // NN*16 quads
    float* buf = (gid < NGR * 16) ? bg : bs;           // halves at natural offsets
    float4* p = ((float4*)buf) + gid;
    float4 v = *p;
    v.x = fmaxf(v.x, 0.f); v.y = fmaxf(v.y, 0.f);
    v.z = fmaxf(v.z, 0.f); v.w = fmaxf(v.w, 0.f);
    *p = v;
}

// ---- fused conv: 8 nodes/warp, unified branch-free gather + degree-grouped transform ----
__global__ void __launch_bounds__(256, 3)
conv_kernel(const float* __restrict__ in_src,
            const float* __restrict__ in_dst,
            float* __restrict__ out,
            int t, int base, int copy,
            const float* __restrict__ Wl,
            const float* __restrict__ bl,
            const float* __restrict__ Wr) {
    int warp = blockIdx.x * 8 + (threadIdx.x >> 5);
    int lane = threadIdx.x & 31;
    int li0 = warp * 8;                     // 8 consecutive local nodes
    const float2* in2  = (const float2*)in_src;
    const float2* ind2 = (const float2*)in_dst;
    float2*       out2 = (float2*)out;
    size_t bkt0 = ((size_t)(t * NGR + li0)) << 7;

    int n[8], d[8];
    unsigned rem = 0;
    int nm = 0;
#pragma unroll
    for (int i = 0; i < 8; i++) {
        int nn = g_cnt[t][li0 + i];
        if (nn > BKT) nn = BKT;
        n[i] = nn;
        d[i] = nn > MAXD ? MAXD : nn;
        if (nn > 0) rem |= 1u << i;
        nm = max(nm, nn);
    }
    if (copy) {                              // lone nodes carry old features
#pragma unroll
        for (int i = 0; i < 8; i++)
            if (n[i] == 0) {
                size_t o = (size_t)(base + li0 + i) * 32 + lane;
                out2[o] = ind2[o];
            }
    }
    if (!rem) return;

    // ---- joint branch-free gather (padded slots hit the zero row) ----
    float2 a[8];
#pragma unroll
    for (int i = 0; i < 8; i++) a[i] = make_float2(0.f, 0.f);
    int nm8 = (nm + 7) & ~7;
    for (int c0 = 0; c0 < nm8; c0 += 32) {
        int idx[8];
#pragma unroll
        for (int i = 0; i < 8; i++)
            idx[i] = __ldg(g_bkt + bkt0 + (size_t)i * 128 + c0 + lane);
        int lim = nm8 - c0; if (lim > 32) lim = 32;
#pragma unroll 4
        for (int e = 0; e < lim; e++) {
#pragma unroll
            for (int i = 0; i < 8; i++) {
                int s = __shfl_sync(0xffffffffu, idx[i], e);
                float2 v = in2[(size_t)s * 32 + lane];
                a[i].x += v.x;
                a[i].y += v.y;
            }
        }
    }

    // ---- transform, grouped by degree bucket (warp-uniform) ----
    float2 hv[8], acc[8];
#pragma unroll
    for (int i = 0; i < 8; i++) {
        hv[i]  = ind2[(size_t)(base + li0 + i) * 32 + lane];
        acc[i] = ((const float2*)(bl + (size_t)d[i] * 64))[lane];
    }
    unsigned todo = rem;
    while (todo) {
        int i0 = __ffs(todo) - 1;
        int dd = 0;
#pragma unroll
        for (int i = 0; i < 8; i++) if (i == i0) dd = d[i];
        unsigned S = 0;
#pragma unroll
        for (int i = 0; i < 8; i++)
            if ((rem >> i & 1) && d[i] == dd) S |= 1u << i;
        todo &= ~S;
        const float2* wl2 = (const float2*)(Wl + (size_t)dd * 4096);
        const float2* wr2 = (const float2*)(Wr + (size_t)dd * 4096);
#pragma unroll 4
        for (int j = 0; j < 32; j++) {
            float2 wle = wl2[(2 * j) * 32 + lane];
            float2 wlo = wl2[(2 * j + 1) * 32 + lane];
            float2 wre = wr2[(2 * j) * 32 + lane];
            float2 wro = wr2[(2 * j + 1) * 32 + lane];
#pragma unroll
            for (int i = 0; i < 8; i++) {
                if (S & (1u << i)) {        // warp-uniform predicate
                    float ax = __shfl_sync(0xffffffffu, a[i].x, j);
                    float ay = __shfl_sync(0xffffffffu, a[i].y, j);
                    float hx = __shfl_sync(0xffffffffu, hv[i].x, j);
                    float hy = __shfl_sync(0xffffffffu, hv[i].y, j);
                    acc[i].x += ax * wle.x + ay * wlo.x + hx * wre.x + hy * wro.x;
                    acc[i].y += ax * wle.y + ay * wlo.y + hx * wre.y + hy * wro.y;
                }
            }
        }
    }
#pragma unroll
    for (int i = 0; i < 8; i++)
        if (rem & (1u << i))
            out2[(size_t)(base + li0 + i) * 32 + lane] = acc[i];
}

// ---------------- pool over ground nodes (scalar f32 atomics) ----------------
__global__ void pool_kernel(const int* __restrict__ batch_idx, const float* __restrict__ buf) {
    int gid = blockIdx.x * blockDim.x + threadIdx.x;  // NG*64
    int i  = gid >> 6;
    int cc = gid & 63;
    int b = __ldg(batch_idx + i);
    atomicAdd(&g_pooled[b * 64 + cc], buf[(size_t)i * 64 + cc]);
}

// ---------------- head: out = relu(pooled@W1+b1) @ W2 + b2 ----------------
__global__ void head_kernel(const float* __restrict__ W1, const float* __restrict__ b1,
                            const float* __restrict__ W2, const float* __restrict__ b2,
                            float* __restrict__ out) {
    int bidx = blockIdx.x;
    int c = threadIdx.x;
    float acc = b1[c];
#pragma unroll 8
    for (int k = 0; k < 64; k++)
        acc += g_pooled[bidx * 64 + k] * W1[k * 64 + c];
    acc = fmaxf(acc, 0.f) * W2[c];
#pragma unroll
    for (int o = 16; o > 0; o >>= 1)
        acc += __shfl_down_sync(0xffffffffu, acc, o);
    __shared__ float s[2];
    if ((threadIdx.x & 31) == 0) s[threadIdx.x >> 5] = acc;
    __syncthreads();
    if (threadIdx.x == 0) out[bidx] = s[0] + s[1] + b2[0];
}

extern "C" void kernel_launch(void* const* d_in, const int* in_sizes, int n_in,
                              void* d_out, int out_size) {
    const float* x          = (const float*)d_in[0];
    const int*   edge_index = (const int*)d_in[1];   // JAX x64-disabled -> int32
    const int*   sub_ei     = (const int*)d_in[2];
    const int*   ns_ei      = (const int*)d_in[3];
    const int*   sn_ei      = (const int*)d_in[4];
    const int*   batch_idx  = (const int*)d_in[7];
    const float* embed_W = (const float*)d_in[8];
    const float* embed_b = (const float*)d_in[9];
    const float* Wl[4] = {(const float*)d_in[10], (const float*)d_in[13],
                          (const float*)d_in[16], (const float*)d_in[19]};
    const float* bl[4] = {(const float*)d_in[11], (const float*)d_in[14],
                          (const float*)d_in[17], (const float*)d_in[20]};
    const float* Wr[4] = {(const float*)d_in[12], (const float*)d_in[15],
                          (const float*)d_in[18], (const float*)d_in[21]};
    const float* W1 = (const float*)d_in[22];
    const float* b1 = (const float*)d_in[23];
    const float* W2 = (const float*)d_in[24];
    const float* b2 = (const float*)d_in[25];
    float* out = (float*)d_out;

    int E0 = in_sizes[1] / 2;   // ground   (t=0)
    int E1 = in_sizes[3] / 2;   // g2s      (t=1)
    int E2 = in_sizes[2] / 2;   // sub      (t=2)
    int E3 = in_sizes[4] / 2;   // s2g      (t=3)

    float* bufs[2];
    cudaGetSymbolAddress((void**)&bufs[0], g_h);
    cudaGetSymbolAddress((void**)&bufs[1], g_h2);

    const int initN = 4 * NGR * BKT / 4 + 4 * NGR + BB * HH + HH;
    init_kernel<<<(initN + 255) / 256, 256>>>();
    embed_kernel<<<NN / 8, 256>>>(x, embed_W, embed_b);
    fill_all_kernel<<<(E0 + E1 + E2 + E3 + 255) / 256, 256>>>(
        edge_index, ns_ei, sub_ei, sn_ei, E0, E1, E2, E3);

    int fg = 0, fs = 0;   // which buffer holds the current ground / sub half
    int bases[4] = {0, NGR, NGR, 0};
    for (int l = 0; l < 2; l++) {
        if (l) relu2_kernel<<<(NN * 16) / 256, 256>>>(bufs[fg], bufs[fs]);
        for (int t = 0; t < 4; t++) {
            size_t woff = (size_t)l * (MAXD + 1) * 64 * 64;
            size_t boff = (size_t)l * (MAXD + 1) * 64;
            const float* src; const float* dst; float* o; int copy;
            if (t == 0)      { src = bufs[fg]; dst = bufs[fg]; o = bufs[1 - fg]; copy = 1; }
            else if (t == 1) { src = bufs[fg]; dst = bufs[fs]; o = bufs[fs];     copy = 0; }
            else if (t == 2) { src = bufs[fs]; dst = bufs[fs]; o = bufs[1 - fs]; copy = 1; }
            else             { src = bufs[fs]; dst = bufs[fg]; o = bufs[fg];     copy = 0; }
            conv_kernel<<<NGR / 64, 256>>>(src, dst, o, t, bases[t], copy,
                                           Wl[t] + woff, bl[t] + boff, Wr[t] + woff);
            if (t == 0) fg ^= 1;
            if (t == 2) fs ^= 1;
        }
    }

    pool_kernel<<<(NGR * 64) / 256, 256>>>(batch_idx, bufs[fg]);
    head_kernel<<<BB, 64>>>(W1, b1, W2, b2, out);
}

// round 15
// speedup vs baseline: 2.0242x; 2.0242x over previous
#include <cuda_runtime.h>
#include <cuda_fp16.h>

#define NN    65536
#define NGR   32768
#define HH    64
#define BB    64
#define MAXD  10
#define BKT   128      // bucket capacity per (type,node); max real degree ~70
#define ZR    NN       // zero-row node id (padding target)

// ---- scratch: device globals (no allocation allowed) ----
__device__ __align__(16) float   g_h [(size_t)(NN + 1) * HH];   // ping fp32 (+ zero row)
__device__ __align__(16) float   g_h2[(size_t)(NN + 1) * HH];   // pong fp32 (+ zero row)
__device__ __align__(16) __half2 g_m [(size_t)(NN + 1) * 32];   // ping fp16 mirror
__device__ __align__(16) __half2 g_m2[(size_t)(NN + 1) * 32];   // pong fp16 mirror
__device__ __align__(16) int     g_bkt[(size_t)4 * NGR * BKT];  // 64MB dst-bucketed src ids
__device__ int   g_cnt[4][NGR];                                 // per-conv-type receive degree
__device__ float g_pooled[BB * HH];

// ---------------- init: pad buckets with ZR, zero counters/pooled/zero-rows ----------------
__global__ void init_kernel() {
    int gid = blockIdx.x * blockDim.x + threadIdx.x;
    const int nbq = 4 * NGR * BKT / 4;
    if (gid < nbq) {
        ((int4*)g_bkt)[gid] = make_int4(ZR, ZR, ZR, ZR);
    } else {
        int r = gid - nbq;
        if (r < 4 * NGR) ((int*)g_cnt)[r] = 0;
        else if (r < 4 * NGR + BB * HH) g_pooled[r - 4 * NGR] = 0.f;
        else if (r < 4 * NGR + BB * HH + HH) {
            int z = r - 4 * NGR - BB * HH;
            g_h [(size_t)ZR * HH + z] = 0.f;
            g_h2[(size_t)ZR * HH + z] = 0.f;
            if (z < 32) {
                g_m [(size_t)ZR * 32 + z] = __floats2half2_rn(0.f, 0.f);
                g_m2[(size_t)ZR * 32 + z] = __floats2half2_rn(0.f, 0.f);
            }
        }
    }
}

// ---------------- single pass: bucket all 4 edge sets ----------------
__global__ void fill_all_kernel(const int* __restrict__ e0, const int* __restrict__ e1,
                                const int* __restrict__ e2, const int* __restrict__ e3,
                                int E0, int E1, int E2, int E3) {
    int e = blockIdx.x * blockDim.x + threadIdx.x;
    const int* ei; int E, t, base;
    if (e < E0)              { ei = e0; E = E0; t = 0; base = 0;   }
    else if ((e -= E0) < E1) { ei = e1; E = E1; t = 1; base = NGR; }
    else if ((e -= E1) < E2) { ei = e2; E = E2; t = 2; base = NGR; }
    else if ((e -= E2) < E3) { ei = e3; E = E3; t = 3; base = 0;   }
    else return;
    int src = __ldg(ei + e);
    int dst = __ldg(ei + E + e);
    int li  = dst - base;
    int slot = atomicAdd(&g_cnt[t][li], 1);
    if (slot < BKT) g_bkt[((size_t)(t * NGR + li) << 7) + slot] = src;
}

// ---------------- embed: h = x @ W(32x64) + b  (fp32 + fp16 mirror) ----------------
__global__ void embed_kernel(const float* __restrict__ x,
                             const float* __restrict__ W,
                             const float* __restrict__ b) {
    int node = blockIdx.x * 8 + (threadIdx.x >> 5);
    int lane = threadIdx.x & 31;
    float xv = x[(size_t)node * 32 + lane];
    int c = lane * 2;
    float2 acc = make_float2(b[c], b[c + 1]);
#pragma unroll 8
    for (int k = 0; k < 32; k++) {
        float xk = __shfl_sync(0xffffffffu, xv, k);
        float2 w = *(const float2*)(W + k * 64 + c);
        acc.x += xk * w.x;
        acc.y += xk * w.y;
    }
    *(float2*)(g_h + (size_t)node * 64 + c) = acc;
    g_m[(size_t)node * 32 + lane] = __float22half2_rn(acc);
}

// ---------------- relu on both current halves (fp32 + mirrors) ----------------
__global__ void relu2_kernel(float* bg, float* bs, __half2* mg, __half2* ms) {
    int gid = blockIdx.x * blockDim.x + threadIdx.x;   // NN*16 quads
    float*   buf = (gid < NGR * 16) ? bg : bs;
    __half2* mir = (gid < NGR * 16) ? mg : ms;
    float4* p = ((float4*)buf) + gid;
    float4 v = *p;
    v.x = fmaxf(v.x, 0.f); v.y = fmaxf(v.y, 0.f);
    v.z = fmaxf(v.z, 0.f); v.w = fmaxf(v.w, 0.f);
    *p = v;
    mir[gid * 2]     = __floats2half2_rn(v.x, v.y);
    mir[gid * 2 + 1] = __floats2half2_rn(v.z, v.w);
}

// ---- fused conv: 4 nodes/warp, fp16 gather, degree-grouped transform (no serial path) ----
__global__ void __launch_bounds__(256, 4)
conv_kernel(const __half2* __restrict__ in_m,   // fp16 mirror of src buffer
            const float*   __restrict__ in_dst, // fp32 dst-self buffer
            float*         __restrict__ out,    // fp32 out buffer
            __half2*       __restrict__ out_m,  // fp16 mirror of out buffer
            int t, int base, int copy,
            const float* __restrict__ Wl,
            const float* __restrict__ bl,
            const float* __restrict__ Wr) {
    int warp = blockIdx.x * 8 + (threadIdx.x >> 5);
    int lane = threadIdx.x & 31;
    int li0 = warp * 4;                     // 4 consecutive local nodes
    const float2* ind2 = (const float2*)in_dst;
    float2*       out2 = (float2*)out;
    size_t bkt0 = ((size_t)(t * NGR + li0)) << 7;

    int n[4], d[4];
    unsigned rem = 0;
    int nm = 0;
#pragma unroll
    for (int i = 0; i < 4; i++) {
        int nn = g_cnt[t][li0 + i];
        if (nn > BKT) nn = BKT;
        n[i] = nn;
        d[i] = nn > MAXD ? MAXD : nn;
        if (nn > 0) rem |= 1u << i;
        nm = max(nm, nn);
    }
    if (copy) {                              // lone nodes carry old features
#pragma unroll
        for (int i = 0; i < 4; i++)
            if (n[i] == 0) {
                size_t o = (size_t)(base + li0 + i) * 32 + lane;
                float2 v = ind2[o];
                out2[o] = v;
                out_m[o] = __float22half2_rn(v);
            }
    }
    if (!rem) return;

    // ---- joint branch-free fp16 gather (padded slots hit the zero row) ----
    float2 a[4];
#pragma unroll
    for (int i = 0; i < 4; i++) a[i] = make_float2(0.f, 0.f);
    int nm8 = (nm + 7) & ~7;
    for (int c0 = 0; c0 < nm8; c0 += 32) {
        int idx[4];
#pragma unroll
        for (int i = 0; i < 4; i++)
            idx[i] = __ldg(g_bkt + bkt0 + (size_t)i * 128 + c0 + lane);
        int lim = nm8 - c0; if (lim > 32) lim = 32;
#pragma unroll 8
        for (int e = 0; e < lim; e++) {
#pragma unroll
            for (int i = 0; i < 4; i++) {
                int s = __shfl_sync(0xffffffffu, idx[i], e);
                float2 v = __half22float2(in_m[(size_t)s * 32 + lane]);
                a[i].x += v.x;
                a[i].y += v.y;
            }
        }
    }

    // ---- transform, grouped by degree bucket (warp-uniform) ----
    float2 hv[4], acc[4];
#pragma unroll
    for (int i = 0; i < 4; i++) {
        hv[i]  = ind2[(size_t)(base + li0 + i) * 32 + lane];
        acc[i] = ((const float2*)(bl + (size_t)d[i] * 64))[lane];
    }
    unsigned todo = rem;
    while (todo) {
        int i0 = __ffs(todo) - 1;
        int dd = 0;
#pragma unroll
        for (int i = 0; i < 4; i++) if (i == i0) dd = d[i];
        unsigned S = 0;
#pragma unroll
        for (int i = 0; i < 4; i++)
            if ((rem >> i & 1) && d[i] == dd) S |= 1u << i;
        todo &= ~S;
        const float2* wl2 = (const float2*)(Wl + (size_t)dd * 4096);
        const float2* wr2 = (const float2*)(Wr + (size_t)dd * 4096);
#pragma unroll 4
        for (int j = 0; j < 32; j++) {
            float2 wle = wl2[(2 * j) * 32 + lane];
            float2 wlo = wl2[(2 * j + 1) * 32 + lane];
            float2 wre = wr2[(2 * j) * 32 + lane];
            float2 wro = wr2[(2 * j + 1) * 32 + lane];
#pragma unroll
            for (int i = 0; i < 4; i++) {
                if (S & (1u << i)) {        // warp-uniform predicate
                    float ax = __shfl_sync(0xffffffffu, a[i].x, j);
                    float ay = __shfl_sync(0xffffffffu, a[i].y, j);
                    float hx = __shfl_sync(0xffffffffu, hv[i].x, j);
                    float hy = __shfl_sync(0xffffffffu, hv[i].y, j);
                    acc[i].x += ax * wle.x + ay * wlo.x + hx * wre.x + hy * wro.x;
                    acc[i].y += ax * wle.y + ay * wlo.y + hx * wre.y + hy * wro.y;
                }
            }
        }
    }
#pragma unroll
    for (int i = 0; i < 4; i++)
        if (rem & (1u << i)) {
            size_t o = (size_t)(base + li0 + i) * 32 + lane;
            out2[o] = acc[i];
            out_m[o] = __float22half2_rn(acc[i]);
        }
}

// ---------------- pool over ground nodes (scalar f32 atomics) ----------------
__global__ void pool_kernel(const int* __restrict__ batch_idx, const float* __restrict__ buf) {
    int gid = blockIdx.x * blockDim.x + threadIdx.x;  // NG*64
    int i  = gid >> 6;
    int cc = gid & 63;
    int b = __ldg(batch_idx + i);
    atomicAdd(&g_pooled[b * 64 + cc], buf[(size_t)i * 64 + cc]);
}

// ---------------- head: out = relu(pooled@W1+b1) @ W2 + b2 ----------------
__global__ void head_kernel(const float* __restrict__ W1, const float* __restrict__ b1,
                            const float* __restrict__ W2, const float* __restrict__ b2,
                            float* __restrict__ out) {
    int bidx = blockIdx.x;
    int c = threadIdx.x;
    float acc = b1[c];
#pragma unroll 8
    for (int k = 0; k < 64; k++)
        acc += g_pooled[bidx * 64 + k] * W1[k * 64 + c];
    acc = fmaxf(acc, 0.f) * W2[c];
#pragma unroll
    for (int o = 16; o > 0; o >>= 1)
        acc += __shfl_down_sync(0xffffffffu, acc, o);
    __shared__ float s[2];
    if ((threadIdx.x & 31) == 0) s[threadIdx.x >> 5] = acc;
    __syncthreads();
    if (threadIdx.x == 0) out[bidx] = s[0] + s[1] + b2[0];
}

extern "C" void kernel_launch(void* const* d_in, const int* in_sizes, int n_in,
                              void* d_out, int out_size) {
    const float* x          = (const float*)d_in[0];
    const int*   edge_index = (const int*)d_in[1];   // JAX x64-disabled -> int32
    const int*   sub_ei     = (const int*)d_in[2];
    const int*   ns_ei      = (const int*)d_in[3];
    const int*   sn_ei      = (const int*)d_in[4];
    const int*   batch_idx  = (const int*)d_in[7];
    const float* embed_W = (const float*)d_in[8];
    const float* embed_b = (const float*)d_in[9];
    const float* Wl[4] = {(const float*)d_in[10], (const float*)d_in[13],
                          (const float*)d_in[16], (const float*)d_in[19]};
    const float* bl[4] = {(const float*)d_in[11], (const float*)d_in[14],
                          (const float*)d_in[17], (const float*)d_in[20]};
    const float* Wr[4] = {(const float*)d_in[12], (const float*)d_in[15],
                          (const float*)d_in[18], (const float*)d_in[21]};
    const float* W1 = (const float*)d_in[22];
    const float* b1 = (const float*)d_in[23];
    const float* W2 = (const float*)d_in[24];
    const float* b2 = (const float*)d_in[25];
    float* out = (float*)d_out;

    int E0 = in_sizes[1] / 2;   // ground   (t=0)
    int E1 = in_sizes[3] / 2;   // g2s      (t=1)
    int E2 = in_sizes[2] / 2;   // sub      (t=2)
    int E3 = in_sizes[4] / 2;   // s2g      (t=3)

    float* bufs[2]; __half2* mirs[2];
    cudaGetSymbolAddress((void**)&bufs[0], g_h);
    cudaGetSymbolAddress((void**)&bufs[1], g_h2);
    cudaGetSymbolAddress((void**)&mirs[0], g_m);
    cudaGetSymbolAddress((void**)&mirs[1], g_m2);

    const int initN = 4 * NGR * BKT / 4 + 4 * NGR + BB * HH + HH;
    init_kernel<<<(initN + 255) / 256, 256>>>();
    embed_kernel<<<NN / 8, 256>>>(x, embed_W, embed_b);
    fill_all_kernel<<<(E0 + E1 + E2 + E3 + 255) / 256, 256>>>(
        edge_index, ns_ei, sub_ei, sn_ei, E0, E1, E2, E3);

    int fg = 0, fs = 0;   // which buffer holds the current ground / sub half
    int bases[4] = {0, NGR, NGR, 0};
    for (int l = 0; l < 2; l++) {
        if (l) relu2_kernel<<<(NN * 16) / 256, 256>>>(bufs[fg], bufs[fs], mirs[fg], mirs[fs]);
        for (int t = 0; t < 4; t++) {
            size_t woff = (size_t)l * (MAXD + 1) * 64 * 64;
            size_t boff = (size_t)l * (MAXD + 1) * 64;
            int sM, dB, oB, copy;
            if (t == 0)      { sM = fg; dB = fg; oB = 1 - fg; copy = 1; }
            else if (t == 1) { sM = fg; dB = fs; oB = fs;     copy = 0; }
            else if (t == 2) { sM = fs; dB = fs; oB = 1 - fs; copy = 1; }
            else             { sM = fs; dB = fg; oB = fg;     copy = 0; }
            conv_kernel<<<NGR / 32, 256>>>(mirs[sM], bufs[dB], bufs[oB], mirs[oB],
                                           t, bases[t], copy,
                                           Wl[t] + woff, bl[t] + boff, Wr[t] + woff);
            if (t == 0) fg ^= 1;
            if (t == 2) fs ^= 1;
        }
    }

    pool_kernel<<<(NGR * 64) / 256, 256>>>(batch_idx, bufs[fg]);
    head_kernel<<<BB, 64>>>(W1, b1, W2, b2, out);
}

// round 16
// speedup vs baseline: 2.0993x; 1.0371x over previous
#include <cuda_runtime.h>
#include <cuda_fp16.h>

#define NN    65536
#define NGR   32768
#define HH    64
#define BB    64
#define MAXD  10
#define BKT   128      // bucket capacity per (type,node); max real degree ~70
#define ZR    NN       // zero-row node id (padding target)

// ---- scratch: device globals (no allocation allowed) ----
__device__ __align__(16) float   g_h [(size_t)(NN + 1) * HH];   // ping fp32 (+ zero row)
__device__ __align__(16) float   g_h2[(size_t)(NN + 1) * HH];   // pong fp32 (+ zero row)
__device__ __align__(16) __half2 g_m [(size_t)(NN + 1) * 32];   // ping fp16 mirror
__device__ __align__(16) __half2 g_m2[(size_t)(NN + 1) * 32];   // pong fp16 mirror
__device__ __align__(16) int     g_bkt[(size_t)4 * NGR * BKT];  // 64MB dst-bucketed src ids
__device__ int   g_cnt[4][NGR];                                 // per-conv-type receive degree
__device__ float g_pooled[BB * HH];

// ---------------- init: pad buckets with ZR, zero counters/pooled/zero-rows ----------------
__global__ void init_kernel() {
    int gid = blockIdx.x * blockDim.x + threadIdx.x;
    const int nbq = 4 * NGR * BKT / 4;
    if (gid < nbq) {
        ((int4*)g_bkt)[gid] = make_int4(ZR, ZR, ZR, ZR);
    } else {
        int r = gid - nbq;
        if (r < 4 * NGR) ((int*)g_cnt)[r] = 0;
        else if (r < 4 * NGR + BB * HH) g_pooled[r - 4 * NGR] = 0.f;
        else if (r < 4 * NGR + BB * HH + HH) {
            int z = r - 4 * NGR - BB * HH;
            g_h [(size_t)ZR * HH + z] = 0.f;
            g_h2[(size_t)ZR * HH + z] = 0.f;
            if (z < 32) {
                g_m [(size_t)ZR * 32 + z] = __floats2half2_rn(0.f, 0.f);
                g_m2[(size_t)ZR * 32 + z] = __floats2half2_rn(0.f, 0.f);
            }
        }
    }
}

// ---------------- single pass: bucket all 4 edge sets ----------------
__global__ void fill_all_kernel(const int* __restrict__ e0, const int* __restrict__ e1,
                                const int* __restrict__ e2, const int* __restrict__ e3,
                                int E0, int E1, int E2, int E3) {
    int e = blockIdx.x * blockDim.x + threadIdx.x;
    const int* ei; int E, t, base;
    if (e < E0)              { ei = e0; E = E0; t = 0; base = 0;   }
    else if ((e -= E0) < E1) { ei = e1; E = E1; t = 1; base = NGR; }
    else if ((e -= E1) < E2) { ei = e2; E = E2; t = 2; base = NGR; }
    else if ((e -= E2) < E3) { ei = e3; E = E3; t = 3; base = 0;   }
    else return;
    int src = __ldg(ei + e);
    int dst = __ldg(ei + E + e);
    int li  = dst - base;
    int slot = atomicAdd(&g_cnt[t][li], 1);
    if (slot < BKT) g_bkt[((size_t)(t * NGR + li) << 7) + slot] = src;
}

// ---------------- embed: h = x @ W(32x64) + b  (fp32 + fp16 mirror) ----------------
__global__ void embed_kernel(const float* __restrict__ x,
                             const float* __restrict__ W,
                             const float* __restrict__ b) {
    int node = blockIdx.x * 8 + (threadIdx.x >> 5);
    int lane = threadIdx.x & 31;
    float xv = x[(size_t)node * 32 + lane];
    int c = lane * 2;
    float2 acc = make_float2(b[c], b[c + 1]);
#pragma unroll 8
    for (int k = 0; k < 32; k++) {
        float xk = __shfl_sync(0xffffffffu, xv, k);
        float2 w = *(const float2*)(W + k * 64 + c);
        acc.x += xk * w.x;
        acc.y += xk * w.y;
    }
    *(float2*)(g_h + (size_t)node * 64 + c) = acc;
    g_m[(size_t)node * 32 + lane] = __float22half2_rn(acc);
}

// ---------------- relu on both current halves (fp32 + mirrors) ----------------
__global__ void relu2_kernel(float* bg, float* bs, __half2* mg, __half2* ms) {
    int gid = blockIdx.x * blockDim.x + threadIdx.x;   // NN*16 quads
    float*   buf = (gid < NGR * 16) ? bg : bs;
    __half2* mir = (gid < NGR * 16) ? mg : ms;
    float4* p = ((float4*)buf) + gid;
    float4 v = *p;
    v.x = fmaxf(v.x, 0.f); v.y = fmaxf(v.y, 0.f);
    v.z = fmaxf(v.z, 0.f); v.w = fmaxf(v.w, 0.f);
    *p = v;
    mir[gid * 2]     = __floats2half2_rn(v.x, v.y);
    mir[gid * 2 + 1] = __floats2half2_rn(v.z, v.w);
}

// ---- fused conv: 4 nodes/warp, fp16 gather, smem-broadcast degree-grouped transform ----
__global__ void __launch_bounds__(256, 5)
conv_kernel(const __half2* __restrict__ in_m,   // fp16 mirror of src buffer
            const float*   __restrict__ in_dst, // fp32 dst-self buffer
            float*         __restrict__ out,    // fp32 out buffer
            __half2*       __restrict__ out_m,  // fp16 mirror of out buffer
            int t, int base, int copy,
            const float* __restrict__ Wl,
            const float* __restrict__ bl,
            const float* __restrict__ Wr) {
    __shared__ float2 s_a[8][4][32];        // per-warp staged agg vectors
    __shared__ float2 s_h[8][4][32];        // per-warp staged self vectors
    int w    = threadIdx.x >> 5;
    int warp = blockIdx.x * 8 + w;
    int lane = threadIdx.x & 31;
    int li0 = warp * 4;                     // 4 consecutive local nodes
    const float2* ind2 = (const float2*)in_dst;
    float2*       out2 = (float2*)out;
    size_t bkt0 = ((size_t)(t * NGR + li0)) << 7;

    int n[4], d[4];
    unsigned rem = 0;
    int nm = 0;
#pragma unroll
    for (int i = 0; i < 4; i++) {
        int nn = g_cnt[t][li0 + i];
        if (nn > BKT) nn = BKT;
        n[i] = nn;
        d[i] = nn > MAXD ? MAXD : nn;
        if (nn > 0) rem |= 1u << i;
        nm = max(nm, nn);
    }
    if (copy) {                              // lone nodes carry old features
#pragma unroll
        for (int i = 0; i < 4; i++)
            if (n[i] == 0) {
                size_t o = (size_t)(base + li0 + i) * 32 + lane;
                float2 v = ind2[o];
                out2[o] = v;
                out_m[o] = __float22half2_rn(v);
            }
    }
    if (!rem) return;

    // ---- joint branch-free fp16 gather (padded slots hit the zero row) ----
    float2 a[4];
#pragma unroll
    for (int i = 0; i < 4; i++) a[i] = make_float2(0.f, 0.f);
    int nm8 = (nm + 7) & ~7;
    for (int c0 = 0; c0 < nm8; c0 += 32) {
        int idx[4];
#pragma unroll
        for (int i = 0; i < 4; i++)
            idx[i] = __ldg(g_bkt + bkt0 + (size_t)i * 128 + c0 + lane);
        int lim = nm8 - c0; if (lim > 32) lim = 32;
#pragma unroll 8
        for (int e = 0; e < lim; e++) {
#pragma unroll
            for (int i = 0; i < 4; i++) {
                int s = __shfl_sync(0xffffffffu, idx[i], e);
                float2 v = __half22float2(in_m[(size_t)s * 32 + lane]);
                a[i].x += v.x;
                a[i].y += v.y;
            }
        }
    }

    // ---- stage agg + self vectors in smem for broadcast reads ----
    float2 acc[4];
#pragma unroll
    for (int i = 0; i < 4; i++) {
        s_a[w][i][lane] = a[i];
        float2 hvv = ind2[(size_t)(base + li0 + i) * 32 + lane];
        s_h[w][i][lane] = hvv;
        acc[i] = ((const float2*)(bl + (size_t)d[i] * 64))[lane];
    }
    __syncwarp();

    // ---- transform, grouped by degree bucket (warp-uniform), smem broadcasts ----
    unsigned todo = rem;
    while (todo) {
        int i0 = __ffs(todo) - 1;
        int dd = 0;
#pragma unroll
        for (int i = 0; i < 4; i++) if (i == i0) dd = d[i];
        unsigned S = 0;
#pragma unroll
        for (int i = 0; i < 4; i++)
            if ((rem >> i & 1) && d[i] == dd) S |= 1u << i;
        todo &= ~S;
        const float2* wl2 = (const float2*)(Wl + (size_t)dd * 4096);
        const float2* wr2 = (const float2*)(Wr + (size_t)dd * 4096);
#pragma unroll 4
        for (int j = 0; j < 32; j++) {
            float2 wle = wl2[(2 * j) * 32 + lane];
            float2 wlo = wl2[(2 * j + 1) * 32 + lane];
            float2 wre = wr2[(2 * j) * 32 + lane];
            float2 wro = wr2[(2 * j + 1) * 32 + lane];
#pragma unroll
            for (int i = 0; i < 4; i++) {
                if (S & (1u << i)) {        // warp-uniform predicate
                    float2 ap = s_a[w][i][j];   // LDS.64 broadcast
                    float2 hp = s_h[w][i][j];
                    acc[i].x += ap.x * wle.x + ap.y * wlo.x + hp.x * wre.x + hp.y * wro.x;
                    acc[i].y += ap.x * wle.y + ap.y * wlo.y + hp.x * wre.y + hp.y * wro.y;
                }
            }
        }
    }
#pragma unroll
    for (int i = 0; i < 4; i++)
        if (rem & (1u << i)) {
            size_t o = (size_t)(base + li0 + i) * 32 + lane;
            out2[o] = acc[i];
            out_m[o] = __float22half2_rn(acc[i]);
        }
}

// ---------------- pool over ground nodes (scalar f32 atomics) ----------------
__global__ void pool_kernel(const int* __restrict__ batch_idx, const float* __restrict__ buf) {
    int gid = blockIdx.x * blockDim.x + threadIdx.x;  // NG*64
    int i  = gid >> 6;
    int cc = gid & 63;
    int b = __ldg(batch_idx + i);
    atomicAdd(&g_pooled[b * 64 + cc], buf[(size_t)i * 64 + cc]);
}

// ---------------- head: out = relu(pooled@W1+b1) @ W2 + b2 ----------------
__global__ void head_kernel(const float* __restrict__ W1, const float* __restrict__ b1,
                            const float* __restrict__ W2, const float* __restrict__ b2,
                            float* __restrict__ out) {
    int bidx = blockIdx.x;
    int c = threadIdx.x;
    float acc = b1[c];
#pragma unroll 8
    for (int k = 0; k < 64; k++)
        acc += g_pooled[bidx * 64 + k] * W1[k * 64 + c];
    acc = fmaxf(acc, 0.f) * W2[c];
#pragma unroll
    for (int o = 16; o > 0; o >>= 1)
        acc += __shfl_down_sync(0xffffffffu, acc, o);
    __shared__ float s[2];
    if ((threadIdx.x & 31) == 0) s[threadIdx.x >> 5] = acc;
    __syncthreads();
    if (threadIdx.x == 0) out[bidx] = s[0] + s[1] + b2[0];
}

extern "C" void kernel_launch(void* const* d_in, const int* in_sizes, int n_in,
                              void* d_out, int out_size) {
    const float* x          = (const float*)d_in[0];
    const int*   edge_index = (const int*)d_in[1];   // JAX x64-disabled -> int32
    const int*   sub_ei     = (const int*)d_in[2];
    const int*   ns_ei      = (const int*)d_in[3];
    const int*   sn_ei      = (const int*)d_in[4];
    const int*   batch_idx  = (const int*)d_in[7];
    const float* embed_W = (const float*)d_in[8];
    const float* embed_b = (const float*)d_in[9];
    const float* Wl[4] = {(const float*)d_in[10], (const float*)d_in[13],
                          (const float*)d_in[16], (const float*)d_in[19]};
    const float* bl[4] = {(const float*)d_in[11], (const float*)d_in[14],
                          (const float*)d_in[17], (const float*)d_in[20]};
    const float* Wr[4] = {(const float*)d_in[12], (const float*)d_in[15],
                          (const float*)d_in[18], (const float*)d_in[21]};
    const float* W1 = (const float*)d_in[22];
    const float* b1 = (const float*)d_in[23];
    const float* W2 = (const float*)d_in[24];
    const float* b2 = (const float*)d_in[25];
    float* out = (float*)d_out;

    int E0 = in_sizes[1] / 2;   // ground   (t=0)
    int E1 = in_sizes[3] / 2;   // g2s      (t=1)
    int E2 = in_sizes[2] / 2;   // sub      (t=2)
    int E3 = in_sizes[4] / 2;   // s2g      (t=3)

    float* bufs[2]; __half2* mirs[2];
    cudaGetSymbolAddress((void**)&bufs[0], g_h);
    cudaGetSymbolAddress((void**)&bufs[1], g_h2);
    cudaGetSymbolAddress((void**)&mirs[0], g_m);
    cudaGetSymbolAddress((void**)&mirs[1], g_m2);

    const int initN = 4 * NGR * BKT / 4 + 4 * NGR + BB * HH + HH;
    init_kernel<<<(initN + 255) / 256, 256>>>();
    embed_kernel<<<NN / 8, 256>>>(x, embed_W, embed_b);
    fill_all_kernel<<<(E0 + E1 + E2 + E3 + 255) / 256, 256>>>(
        edge_index, ns_ei, sub_ei, sn_ei, E0, E1, E2, E3);

    int fg = 0, fs = 0;   // which buffer holds the current ground / sub half
    int bases[4] = {0, NGR, NGR, 0};
    for (int l = 0; l < 2; l++) {
        if (l) relu2_kernel<<<(NN * 16) / 256, 256>>>(bufs[fg], bufs[fs], mirs[fg], mirs[fs]);
        for (int t = 0; t < 4; t++) {
            size_t woff = (size_t)l * (MAXD + 1) * 64 * 64;
            size_t boff = (size_t)l * (MAXD + 1) * 64;
            int sM, dB, oB, copy;
            if (t == 0)      { sM = fg; dB = fg; oB = 1 - fg; copy = 1; }
            else if (t == 1) { sM = fg; dB = fs; oB = fs;     copy = 0; }
            else if (t == 2) { sM = fs; dB = fs; oB = 1 - fs; copy = 1; }
            else             { sM = fs; dB = fg; oB = fg;     copy = 0; }
            conv_kernel<<<NGR / 32, 256>>>(mirs[sM], bufs[dB], bufs[oB], mirs[oB],
                                           t, bases[t], copy,
                                           Wl[t] + woff, bl[t] + boff, Wr[t] + woff);
            if (t == 0) fg ^= 1;
            if (t == 2) fs ^= 1;
        }
    }

    pool_kernel<<<(NGR * 64) / 256, 256>>>(batch_idx, bufs[fg]);
    head_kernel<<<BB, 64>>>(W1, b1, W2, b2, out);
}